// round 6
// baseline (speedup 1.0000x reference)
#include <cuda_runtime.h>

// CASSI forward, pipelined row-streaming kernel.
//
// Block = one m row. Loop over 8 tiles of TN=128 n-rows:
//   - issue 16 aligned LDG.128 per thread for tile t+1 (pure sequential stream)
//   - reduce tile t from smem: thread tid accumulates
//       accL (output c = n0+tid, terms l <= tid) and
//       accH (carry for c = n0+TN+tid, terms l > tid)
//     via rotation l=(tid+j)&63 -> exactly 64 uniform LDS+FADD steps/thread.
//   - fold ca and STS tile t+1 into the other buffer.
// Carry rides in a register across tiles: no atomics, no zero-init.

#define MM   1024
#define NN   1024
#define LL   64
#define OUTC (NN + LL - 1)          // 1087
#define TN   128                    // n-rows per tile
#define TPB  128                    // threads per block
#define NTIL (NN / TN)              // 8
#define V4PT (TN * LL / 4 / TPB)    // 16 float4 per thread per tile
#define SMEM_BYTES ((2 * TN * LL + NN) * sizeof(float))   // 69632 B

__global__ __launch_bounds__(TPB)
void cassi_pipe_kernel(const float* __restrict__ x,
                       const float* __restrict__ ca,
                       float* __restrict__ y)
{
    extern __shared__ float smem[];
    float* buf0 = smem;                  // TN*LL
    float* buf1 = smem + TN * LL;        // TN*LL
    float* sca  = smem + 2 * TN * LL;    // NN

    const int m   = blockIdx.x;
    const int tid = threadIdx.x;

    // Stage the full ca row once (4 KB).
    #pragma unroll
    for (int i = tid; i < NN; i += TPB)
        sca[i] = ca[m * NN + i];
    __syncthreads();

    const float*  xrow = x + (size_t)m * (NN * LL);
    float*        yrow = y + (size_t)m * OUTC;
    const float4* xv   = (const float4*)xrow;

    // Prologue: tile 0 -> buf0
    float4 v[V4PT];
    #pragma unroll
    for (int k = 0; k < V4PT; ++k) v[k] = xv[tid + k * TPB];
    #pragma unroll
    for (int k = 0; k < V4PT; ++k) {
        const float s = sca[(tid + k * TPB) >> 4];   // 16 float4 per n-row
        v[k].x *= s; v[k].y *= s; v[k].z *= s; v[k].w *= s;
    }
    #pragma unroll
    for (int k = 0; k < V4PT; ++k) ((float4*)buf0)[tid + k * TPB] = v[k];
    __syncthreads();

    float carry = 0.0f;

    #pragma unroll 1
    for (int t = 0; t < NTIL; ++t) {
        float* cur = (t & 1) ? buf1 : buf0;
        float* nxt = (t & 1) ? buf0 : buf1;

        // Issue next tile's loads first (latency hidden under the reduce).
        if (t < NTIL - 1) {
            const float4* xt = (const float4*)(xrow + (size_t)(t + 1) * TN * LL);
            #pragma unroll
            for (int k = 0; k < V4PT; ++k) v[k] = xt[tid + k * TPB];
        }

        // Reduce tile t: 64 uniform steps per thread.
        float accL = carry;      // carry==0 for tid >= LL-1
        float accH = 0.0f;
        #pragma unroll
        for (int j = 0; j < LL; ++j) {
            const int  l   = (tid + j) & (LL - 1);
            const bool low = (l <= tid);
            const int  n   = low ? (tid - l) : (tid + TN - l);
            const float val = cur[n * LL + l];
            if (low) accL += val; else accH += val;
        }
        yrow[t * TN + tid] = accL;
        carry = accH;

        // Fold ca and commit next tile to the other buffer.
        if (t < NTIL - 1) {
            const int nb = (t + 1) * TN;
            #pragma unroll
            for (int k = 0; k < V4PT; ++k) {
                const float s = sca[nb + ((tid + k * TPB) >> 4)];
                v[k].x *= s; v[k].y *= s; v[k].z *= s; v[k].w *= s;
            }
            #pragma unroll
            for (int k = 0; k < V4PT; ++k) ((float4*)nxt)[tid + k * TPB] = v[k];
        }
        __syncthreads();
    }

    // Tail: outputs c in [NN, NN+LL-1) come from the final carry.
    if (tid < LL - 1)
        yrow[NN + tid] = carry;
}

extern "C" void kernel_launch(void* const* d_in, const int* in_sizes, int n_in,
                              void* d_out, int out_size)
{
    const float* x  = (const float*)d_in[0];
    const float* ca = (const float*)d_in[1];
    float* y        = (float*)d_out;

    cudaFuncSetAttribute(cassi_pipe_kernel,
                         cudaFuncAttributeMaxDynamicSharedMemorySize,
                         (int)SMEM_BYTES);

    cassi_pipe_kernel<<<MM, TPB, SMEM_BYTES>>>(x, ca, y);
}

// round 7
// speedup vs baseline: 1.5134x; 1.5134x over previous
#include <cuda_runtime.h>
#include <cstdint>

// CASSI forward: TMA (cp.async.bulk) double-buffered pipeline + carry reduce.
//
// Block = one m row (persistent over 8 tiles of 128 n-rows, 32KB each).
//  - tiles stream into 2 smem buffers via cp.async.bulk + mbarrier
//    (zero register pressure, deep in-flight bytes)
//  - reduce (from R6, proven correct): thread tid accumulates
//      accL -> output c = t*128 + tid   (terms with l <= tid)
//      accH -> carry for c = (t+1)*128 + tid  (terms with l > tid)
//    rotation l = (tid+j)&63 -> conflict-free LDS; ca folded in the FMA.
//  - carry rides in a register across tiles: no atomics, no zero-init.

#define MM   1024
#define NN   1024
#define LL   64
#define OUTC (NN + LL - 1)            // 1087
#define TN   128                      // n-rows per tile
#define TPB  128                      // threads per block (== TN)
#define NTIL (NN / TN)                // 8
#define TILE_BYTES (TN * LL * 4)      // 32768
#define SMEM_DYN   (2 * TN * LL * 4 + NN * 4)   // 69632 B

__device__ __forceinline__ uint32_t smem_u32(const void* p)
{
    uint32_t a;
    asm("{ .reg .u64 t; cvta.to.shared.u64 t, %1; cvt.u32.u64 %0, t; }"
        : "=r"(a) : "l"(p));
    return a;
}

__device__ __forceinline__ void mbar_init(uint32_t mb, uint32_t count)
{
    asm volatile("mbarrier.init.shared.b64 [%0], %1;" :: "r"(mb), "r"(count) : "memory");
}

__device__ __forceinline__ void tma_tile(uint32_t dst, const float* src, uint32_t mb)
{
    asm volatile("mbarrier.arrive.expect_tx.shared.b64 _, [%0], %1;"
                 :: "r"(mb), "r"((uint32_t)TILE_BYTES) : "memory");
    asm volatile("cp.async.bulk.shared::cta.global.mbarrier::complete_tx::bytes "
                 "[%0], [%1], %2, [%3];"
                 :: "r"(dst), "l"(src), "r"((uint32_t)TILE_BYTES), "r"(mb) : "memory");
}

__device__ __forceinline__ void mbar_wait(uint32_t mb, uint32_t parity)
{
    uint32_t done;
    asm volatile(
        "{\n\t"
        ".reg .pred p;\n\t"
        "mbarrier.try_wait.parity.acquire.cta.shared::cta.b64 p, [%1], %2;\n\t"
        "selp.b32 %0, 1, 0, p;\n\t"
        "}"
        : "=r"(done) : "r"(mb), "r"(parity) : "memory");
    if (!done) {
        asm volatile(
            "{\n\t"
            ".reg .pred P1;\n\t"
            "W%=:\n\t"
            "mbarrier.try_wait.parity.acquire.cta.shared::cta.b64 P1, [%0], %1;\n\t"
            "@P1 bra D%=;\n\t"
            "bra W%=;\n\t"
            "D%=:\n\t"
            "}"
            :: "r"(mb), "r"(parity) : "memory");
    }
}

__global__ __launch_bounds__(TPB)
void cassi_tma_kernel(const float* __restrict__ x,
                      const float* __restrict__ ca,
                      float* __restrict__ y)
{
    extern __shared__ float smem[];
    float* buf0 = smem;                  // TN*LL floats (32KB)
    float* buf1 = smem + TN * LL;        // TN*LL floats (32KB)
    float* sca  = smem + 2 * TN * LL;    // NN floats (4KB)
    __shared__ __align__(8) uint64_t mbar_store[2];

    const int m   = blockIdx.x;
    const int tid = threadIdx.x;

    const float* xrow = x + (size_t)m * (NN * LL);
    float*       yrow = y + (size_t)m * OUTC;

    const uint32_t mb0 = smem_u32(&mbar_store[0]);
    const uint32_t mb1 = smem_u32(&mbar_store[1]);
    const uint32_t b0  = smem_u32(buf0);
    const uint32_t b1  = smem_u32(buf1);

    if (tid == 0) {
        mbar_init(mb0, 1);
        mbar_init(mb1, 1);
    }
    __syncthreads();

    if (tid == 0) {
        tma_tile(b0, xrow,           mb0);   // tile 0
        tma_tile(b1, xrow + TN * LL, mb1);   // tile 1
    }

    // Stage full ca row (coalesced, overlaps with in-flight TMA).
    #pragma unroll
    for (int i = tid; i < NN; i += TPB)
        sca[i] = ca[m * NN + i];
    __syncthreads();

    float carry = 0.0f;

    #pragma unroll 1
    for (int t = 0; t < NTIL; ++t) {
        const uint32_t mb     = (t & 1) ? mb1 : mb0;
        const float*   cur    = (t & 1) ? buf1 : buf0;
        const uint32_t parity = (t >> 1) & 1;

        mbar_wait(mb, parity);

        const float* scat = sca + t * TN;
        float accL = carry;      // carry == 0 for tid >= LL-1
        float accH = 0.0f;
        #pragma unroll
        for (int j = 0; j < LL; ++j) {
            const int  l   = (tid + j) & (LL - 1);
            const bool low = (l <= tid);
            const int  n   = low ? (tid - l) : (tid + TN - l);
            const float v  = cur[n * LL + l];
            if (low) accL = fmaf(v, scat[n], accL);
            else     accH = fmaf(v, scat[n], accH);
        }
        yrow[t * TN + tid] = accL;
        carry = accH;

        __syncthreads();   // all threads done reading `cur`

        if (t + 2 < NTIL && tid == 0) {
            const uint32_t db = (t & 1) ? b1 : b0;
            tma_tile(db, xrow + (size_t)(t + 2) * TN * LL, mb);
        }
    }

    // Tail: outputs c in [NN, NN+LL-1) come from the final carry.
    if (tid < LL - 1)
        yrow[NN + tid] = carry;
}

extern "C" void kernel_launch(void* const* d_in, const int* in_sizes, int n_in,
                              void* d_out, int out_size)
{
    const float* x  = (const float*)d_in[0];
    const float* ca = (const float*)d_in[1];
    float* y        = (float*)d_out;

    cudaFuncSetAttribute(cassi_tma_kernel,
                         cudaFuncAttributeMaxDynamicSharedMemorySize,
                         (int)SMEM_DYN);

    cassi_tma_kernel<<<MM, TPB, SMEM_DYN>>>(x, ca, y);
}